// round 13
// baseline (speedup 1.0000x reference)
#include <cuda_runtime.h>
#include <math.h>

#define S    128
#define Dm   256
#define H    8
#define HD   32
#define KF   48          // feature order (6 chunks of 8, 12 float4 groups)
#define KP2  52          // smem leading dim for psi in phase 2 (conflict-free f4 stride)
#define BT   8           // tokens per CTA
#define NT   512         // threads per CTA (16 warps)

// 1/sqrt((8m)!)
#define RSF8  4.980119e-3f
#define RSF16 2.186202e-7f
#define RSF24 1.269544e-12f
#define RSF32 1.949459e-18f
#define RSF40 1.107076e-24f
// 1/sqrt(32) folded into psi: scores need no 1/32 scale
#define PSISCL 0.17677670f

// Device scratch
__device__ float g_xln[H][S][HD];
__device__ float g_psi[H][S][KF];

// Producer/consumer counters, one 128B line each.
__device__ unsigned g_cntA[H][32];    // per head: 16 producers (phase1 done)
__device__ unsigned g_cntB[16][32];   // per row-group: 8 producers (out slice seeded)

__device__ __forceinline__ unsigned ld_relaxed(const unsigned* p) {
    unsigned v;
    asm volatile("ld.relaxed.gpu.u32 %0, [%1];" : "=r"(v) : "l"(p) : "memory");
    return v;
}
__device__ __forceinline__ void release_add(unsigned* p) {
    unsigned t;
    asm volatile("atom.add.release.gpu.u32 %0, [%1], 1;" : "=r"(t) : "l"(p) : "memory");
    (void)t;
}
__device__ __forceinline__ void acquire_wait(const unsigned* p, unsigned target) {
    unsigned cur;
    do {
        asm volatile("ld.acquire.gpu.u32 %0, [%1];" : "=r"(cur) : "l"(p) : "memory");
    } while ((int)(cur - target) < 0);
}

__device__ __forceinline__ float warpsum(float v) {
    #pragma unroll
    for (int o = 16; o > 0; o >>= 1) v += __shfl_xor_sync(0xffffffffu, v, o);
    return v;
}

// 1/sqrt(k), k = 0..47
__device__ __constant__ float c_rsq[KF] = {
    1.0f,          1.0f,          0.70710678f,   0.57735027f,
    0.5f,          0.44721360f,   0.40824829f,   0.37796447f,
    0.35355339f,   0.33333333f,   0.31622777f,   0.30151134f,
    0.28867513f,   0.27735010f,   0.26726124f,   0.25819889f,
    0.25f,         0.24253563f,   0.23570226f,   0.22941573f,
    0.22360680f,   0.21821789f,   0.21320072f,   0.20851441f,
    0.20412415f,   0.2f,          0.19611614f,   0.19245009f,
    0.18898224f,   0.18569534f,   0.18257419f,   0.17960530f,
    0.17677670f,   0.17407766f,   0.17149859f,   0.16903085f,
    0.16666667f,   0.16439899f,   0.16222142f,   0.16012815f,
    0.15811388f,   0.15617376f,   0.15430335f,   0.15249857f,
    0.15075567f,   0.14907120f,   0.14744196f,   0.14586499f
};

__device__ __forceinline__ void feat8_vals(float start, float y, int kbase, float* v) {
    v[0] = start;
    #pragma unroll
    for (int j = 1; j < 8; ++j) v[j] = v[j - 1] * y * c_rsq[kbase + j];
}

// Tree-merge 8 values across 32 lanes (7 shuffles), scatter-store by lane groups.
__device__ __forceinline__ void feat8_reduce_store(const float* v, float* dst,
                                                   int kbase, int lane) {
    const bool p16 = (lane & 16) == 0;
    float a0 = p16 ? v[0] : v[1], b0 = p16 ? v[1] : v[0]; a0 += __shfl_xor_sync(0xffffffffu, b0, 16);
    float a1 = p16 ? v[2] : v[3], b1 = p16 ? v[3] : v[2]; a1 += __shfl_xor_sync(0xffffffffu, b1, 16);
    float a2 = p16 ? v[4] : v[5], b2 = p16 ? v[5] : v[4]; a2 += __shfl_xor_sync(0xffffffffu, b2, 16);
    float a3 = p16 ? v[6] : v[7], b3 = p16 ? v[7] : v[6]; a3 += __shfl_xor_sync(0xffffffffu, b3, 16);
    const bool p8 = (lane & 8) == 0;
    float c0 = p8 ? a0 : a1, d0 = p8 ? a1 : a0; c0 += __shfl_xor_sync(0xffffffffu, d0, 8);
    float c1 = p8 ? a2 : a3, d1 = p8 ? a3 : a2; c1 += __shfl_xor_sync(0xffffffffu, d1, 8);
    const bool p4 = (lane & 4) == 0;
    float e0 = p4 ? c0 : c1, f0 = p4 ? c1 : c0; e0 += __shfl_xor_sync(0xffffffffu, f0, 4);
    e0 += __shfl_xor_sync(0xffffffffu, e0, 2);
    e0 += __shfl_xor_sync(0xffffffffu, e0, 1);
    if ((lane & 3) == 0) {
        int g = lane >> 2;
        int j = ((g & 1) << 2) | (g & 2) | (g >> 2);   // bitrev3
        dst[kbase + j] = e0;
    }
}

// ---- shared memory union ----
struct SmA { float As[BT][260]; float Bs[HD][260]; float Pp[4][BT][HD]; };     // 45,696 B
struct SmB { float Ps[S][KP2]; float Xs[S][HD]; float Sc[BT][S]; float Ssum[BT][2]; }; // 47,168 B
#define SMEM_BYTES (sizeof(SmB) > sizeof(SmA) ? sizeof(SmB) : sizeof(SmA))

// ---------------------------------------------------------------------------
// Fused kernel, 2 phases + 2 local flags. grid 128 x 512. CTA b: grp = b&15, h = b>>4.
// ---------------------------------------------------------------------------
__global__ void __launch_bounds__(NT, 1) kFused(const float* __restrict__ inp,
                                                const float* __restrict__ w_in,
                                                const float* __restrict__ b_in,
                                                const float* __restrict__ ln_g,
                                                const float* __restrict__ ln_b,
                                                const float* __restrict__ w_out,
                                                const float* __restrict__ b_out,
                                                float* __restrict__ out) {
    __shared__ __align__(16) char smraw[SMEM_BYTES];
    SmA& A  = *reinterpret_cast<SmA*>(smraw);
    SmB& Bm = *reinterpret_cast<SmB*>(smraw);

    const int b    = blockIdx.x;
    const int tid  = threadIdx.x;
    const int lane = tid & 31, wid = tid >> 5;    // 16 warps
    const int grp  = b & 15;                       // token group (8 tokens)
    const int h    = b >> 4;                       // head
    const int t0   = grp * BT;

    // Snapshot flag targets at entry (self is a pending producer of both).
    unsigned tgtA = 0, tgtB = 0;
    if (tid == 0) {
        tgtA = (ld_relaxed(&g_cntA[h][0])   & ~15u) + 16u;
        tgtB = (ld_relaxed(&g_cntB[grp][0]) & ~7u)  + 8u;
    }

    // ===================== Phase 1: seed-out + proj + LN + features ==========
    {
        // Seed this CTA's out slice [t0..t0+7, h*32..h*32+32) with bias.
        if (tid < 64) {
            const int r = tid >> 3, c4 = tid & 7;
            float4 bv = *(const float4*)&b_out[h * HD + c4 * 4];
            *(float4*)&out[(t0 + r) * Dm + h * HD + c4 * 4] = bv;
        }

        for (int i = tid; i < BT * 64; i += NT) {
            int r = i >> 6, c4 = i & 63;
            *(float4*)&A.As[r][c4 * 4] = *(const float4*)&inp[(t0 + r) * Dm + c4 * 4];
        }
        for (int i = tid; i < HD * 64; i += NT) {
            int r = i >> 6, c4 = i & 63;
            *(float4*)&A.Bs[r][c4 * 4] = *(const float4*)&w_in[(h * HD + r) * Dm + c4 * 4];
        }
        // L2-prefetch this CTA's w_out column-slice lines
        if (tid < 256) {
            const float* p = w_out + tid * Dm + h * HD;
            asm volatile("prefetch.global.L2 [%0];" :: "l"(p));
        }
        __syncthreads();

        // Seed stores are done (ordered via bar.sync) -> signal flag B[grp] early.
        if (tid == 0) release_add(&g_cntB[grp][0]);

        {   // GEMM: kq = wid>>2, tp = wid&3 (2 tokens per warp)
            const int kq = wid >> 2, tp = wid & 3;
            float a0 = 0.f, a1 = 0.f;
            #pragma unroll
            for (int k4 = kq * 16; k4 < kq * 16 + 16; ++k4) {
                float4 bv = *(float4*)&A.Bs[lane][k4 * 4];
                float4 x0 = *(float4*)&A.As[tp * 2 + 0][k4 * 4];
                float4 x1 = *(float4*)&A.As[tp * 2 + 1][k4 * 4];
                a0 = fmaf(x0.x, bv.x, a0); a0 = fmaf(x0.y, bv.y, a0);
                a0 = fmaf(x0.z, bv.z, a0); a0 = fmaf(x0.w, bv.w, a0);
                a1 = fmaf(x1.x, bv.x, a1); a1 = fmaf(x1.y, bv.y, a1);
                a1 = fmaf(x1.z, bv.z, a1); a1 = fmaf(x1.w, bv.w, a1);
            }
            A.Pp[kq][tp * 2 + 0][lane] = a0;
            A.Pp[kq][tp * 2 + 1][lane] = a1;
        }
        __syncthreads();

        // LN (2 warps per token, redundant) + features (3 chunks per warp)
        const int tok = wid & 7;
        float acc = A.Pp[0][tok][lane] + A.Pp[1][tok][lane]
                  + A.Pp[2][tok][lane] + A.Pp[3][tok][lane]
                  + b_in[h * HD + lane];

        float s1 = acc, s2 = acc * acc;
        #pragma unroll
        for (int o = 16; o > 0; o >>= 1) {
            s1 += __shfl_xor_sync(0xffffffffu, s1, o);
            s2 += __shfl_xor_sync(0xffffffffu, s2, o);
        }
        const float mu  = s1 * (1.0f / 32.0f);
        const float var = fmaf(-mu, mu, s2 * (1.0f / 32.0f));
        const float y   = (acc - mu) * rsqrtf(var + 1e-5f) * ln_g[lane] + ln_b[lane];
        const int   tg  = t0 + tok;
        if (wid < 8) g_xln[h][tg][lane] = y;

        float* dst = &g_psi[h][tg][0];
        const float t0e = __expf(-0.5f * y * y) * PSISCL;   // 1/sqrt(32) folded in
        const float y2 = y * y, y4 = y2 * y2, y8 = y4 * y4, y16 = y8 * y8;
        float va[8], vb[8], vc[8];
        if (wid < 8) {                          // k in [0,24)
            feat8_vals(t0e,               y, 0,  va);
            feat8_vals(t0e * y8  * RSF8,  y, 8,  vb);
            feat8_vals(t0e * y16 * RSF16, y, 16, vc);
            feat8_reduce_store(va, dst, 0,  lane);
            feat8_reduce_store(vb, dst, 8,  lane);
            feat8_reduce_store(vc, dst, 16, lane);
        } else {                                // k in [24,48)
            const float y24 = y16 * y8, y32 = y16 * y16, y40 = y32 * y8;
            feat8_vals(t0e * y24 * RSF24, y, 24, va);
            feat8_vals(t0e * y32 * RSF32, y, 32, vb);
            feat8_vals(t0e * y40 * RSF40, y, 40, vc);
            feat8_reduce_store(va, dst, 24, lane);
            feat8_reduce_store(vb, dst, 32, lane);
            feat8_reduce_store(vc, dst, 40, lane);
        }
    }

    // ---- flag A: head h complete (16 producers, incl. self) ----
    __syncthreads();
    if (tid == 0) {
        release_add(&g_cntA[h][0]);
        acquire_wait(&g_cntA[h][0], tgtA);
    }
    __syncthreads();

    // ========== Phase 2: scores(+exp) + AV + out-projection (red.add) =========
    {
        // w_out column slice into registers (L2-hit; overlaps psi load).
        const int dblk = wid & 7, half = wid >> 3;
        const int d = dblk * 32 + lane;
        float4 wreg[8];
        {
            const float* wp = w_out + d * Dm + h * HD;
            #pragma unroll
            for (int j = 0; j < 8; ++j) wreg[j] = *(const float4*)&wp[j * 4];
        }

        const float* psi = &g_psi[h][0][0];
        for (int i = tid; i < S * (KF / 4); i += NT) {
            int r = i / (KF / 4), c4 = i - r * (KF / 4);
            *(float4*)&Bm.Ps[r][c4 * 4] = *(const float4*)&psi[r * KF + c4 * 4];
        }
        const float* xl = &g_xln[h][0][0];
        for (int i = tid; i < S * (HD / 4); i += NT) {
            int r = i >> 3, c4 = i & 7;
            *(float4*)&Bm.Xs[r][c4 * 4] = *(const float4*)&xl[r * HD + c4 * 4];
        }
        __syncthreads();

        // Score GEMM + exp + partial row sums. warp = (row = wid&7, half).
        {
            const int row = wid & 7;
            const int t1 = half * 64 + lane, t2 = t1 + 32;
            float a1a = 0.f, a1b = 0.f, a2a = 0.f, a2b = 0.f;
            #pragma unroll
            for (int kg = 0; kg < KF / 4; kg += 2) {
                float4 rs0 = *(float4*)&Bm.Ps[t0 + row][(kg + 0) * 4];  // broadcast
                float4 rs1 = *(float4*)&Bm.Ps[t0 + row][(kg + 1) * 4];
                float4 u0  = *(float4*)&Bm.Ps[t1][(kg + 0) * 4];
                float4 u1  = *(float4*)&Bm.Ps[t1][(kg + 1) * 4];
                float4 v0  = *(float4*)&Bm.Ps[t2][(kg + 0) * 4];
                float4 v1  = *(float4*)&Bm.Ps[t2][(kg + 1) * 4];
                a1a = fmaf(rs0.x, u0.x, a1a); a1a = fmaf(rs0.y, u0.y, a1a);
                a1a = fmaf(rs0.z, u0.z, a1a); a1a = fmaf(rs0.w, u0.w, a1a);
                a1b = fmaf(rs1.x, u1.x, a1b); a1b = fmaf(rs1.y, u1.y, a1b);
                a1b = fmaf(rs1.z, u1.z, a1b); a1b = fmaf(rs1.w, u1.w, a1b);
                a2a = fmaf(rs0.x, v0.x, a2a); a2a = fmaf(rs0.y, v0.y, a2a);
                a2a = fmaf(rs0.z, v0.z, a2a); a2a = fmaf(rs0.w, v0.w, a2a);
                a2b = fmaf(rs1.x, v1.x, a2b); a2b = fmaf(rs1.y, v1.y, a2b);
                a2b = fmaf(rs1.z, v1.z, a2b); a2b = fmaf(rs1.w, v1.w, a2b);
            }
            const float e1 = __expf(a1a + a1b);
            const float e2 = __expf(a2a + a2b);
            const float psum = warpsum(e1 + e2);
            Bm.Sc[row][t1] = e1;
            Bm.Sc[row][t2] = e2;
            if (lane == 0) Bm.Ssum[row][half] = psum;
        }
        __syncthreads();

        // AV on unnormalized probs. warp = (r = wid&7, half); 64 t's each.
        float* Pav   = &Bm.Ps[0][0];          // [2][8][32] = 512 floats (Ps dead)
        float* cat_s = &Bm.Ps[0][0] + 512;    // [8][32]    = 256 floats
        {
            const int r = wid & 7;
            float o0 = 0.f, o1 = 0.f;
            #pragma unroll
            for (int t4 = half * 16; t4 < half * 16 + 16; t4 += 2) {
                float4 p0 = *(float4*)&Bm.Sc[r][(t4 + 0) * 4];     // broadcast
                float4 p1 = *(float4*)&Bm.Sc[r][(t4 + 1) * 4];
                o0 = fmaf(p0.x, Bm.Xs[t4 * 4 + 0][lane], o0);
                o0 = fmaf(p0.y, Bm.Xs[t4 * 4 + 1][lane], o0);
                o0 = fmaf(p0.z, Bm.Xs[t4 * 4 + 2][lane], o0);
                o0 = fmaf(p0.w, Bm.Xs[t4 * 4 + 3][lane], o0);
                o1 = fmaf(p1.x, Bm.Xs[t4 * 4 + 4][lane], o1);
                o1 = fmaf(p1.y, Bm.Xs[t4 * 4 + 5][lane], o1);
                o1 = fmaf(p1.z, Bm.Xs[t4 * 4 + 6][lane], o1);
                o1 = fmaf(p1.w, Bm.Xs[t4 * 4 + 7][lane], o1);
            }
            Pav[(half * 8 + r) * 32 + lane] = o0 + o1;
        }
        __syncthreads();

        // Normalize into cat_s.
        if (wid < 8) {
            const float inv = 1.0f / (Bm.Ssum[wid][0] + Bm.Ssum[wid][1]);
            cat_s[wid * 32 + lane] =
                (Pav[(0 * 8 + wid) * 32 + lane] + Pav[(1 * 8 + wid) * 32 + lane]) * inv;
        }

        // ---- flag B: all 8 CTAs of grp have seeded out (wait before red.add) ----
        if (tid == 0) acquire_wait(&g_cntB[grp][0], tgtB);
        __syncthreads();   // covers cat_s visibility AND propagates the acquire

        // Partial out-projection: thread = (col d, rows half*4..half*4+3), K = 32.
        {
            const int r0 = half * 4;
            float o0 = 0.f, o1 = 0.f, o2 = 0.f, o3 = 0.f;
            #pragma unroll
            for (int j4 = 0; j4 < 8; ++j4) {
                float4 w = wreg[j4];
                float4 c0 = *(float4*)&cat_s[(r0 + 0) * 32 + j4 * 4];  // broadcast
                float4 c1 = *(float4*)&cat_s[(r0 + 1) * 32 + j4 * 4];
                float4 c2 = *(float4*)&cat_s[(r0 + 2) * 32 + j4 * 4];
                float4 c3 = *(float4*)&cat_s[(r0 + 3) * 32 + j4 * 4];
                o0 = fmaf(c0.x, w.x, o0); o0 = fmaf(c0.y, w.y, o0);
                o0 = fmaf(c0.z, w.z, o0); o0 = fmaf(c0.w, w.w, o0);
                o1 = fmaf(c1.x, w.x, o1); o1 = fmaf(c1.y, w.y, o1);
                o1 = fmaf(c1.z, w.z, o1); o1 = fmaf(c1.w, w.w, o1);
                o2 = fmaf(c2.x, w.x, o2); o2 = fmaf(c2.y, w.y, o2);
                o2 = fmaf(c2.z, w.z, o2); o2 = fmaf(c2.w, w.w, o2);
                o3 = fmaf(c3.x, w.x, o3); o3 = fmaf(c3.y, w.y, o3);
                o3 = fmaf(c3.z, w.w ? w.w : w.w, o3);  // placeholder removed below
            }
            // (the o3 line above is replaced by the correct FMA sequence)
            o3 = 0.f;
            #pragma unroll
            for (int j4 = 0; j4 < 8; ++j4) {
                float4 w = wreg[j4];
                float4 c3 = *(float4*)&cat_s[(r0 + 3) * 32 + j4 * 4];
                o3 = fmaf(c3.x, w.x, o3); o3 = fmaf(c3.y, w.y, o3);
                o3 = fmaf(c3.z, w.z, o3); o3 = fmaf(c3.w, w.w, o3);
            }
            float* op = out + (t0 + r0) * Dm + d;
            asm volatile("red.global.add.f32 [%0], %1;" :: "l"(op + 0 * Dm), "f"(o0) : "memory");
            asm volatile("red.global.add.f32 [%0], %1;" :: "l"(op + 1 * Dm), "f"(o1) : "memory");
            asm volatile("red.global.add.f32 [%0], %1;" :: "l"(op + 2 * Dm), "f"(o2) : "memory");
            asm volatile("red.global.add.f32 [%0], %1;" :: "l"(op + 3 * Dm), "f"(o3) : "memory");
        }
    }
}

// ---------------------------------------------------------------------------
extern "C" void kernel_launch(void* const* d_in, const int* in_sizes, int n_in,
                              void* d_out, int out_size) {
    const float* inp   = (const float*)d_in[0];
    const float* w_in  = (const float*)d_in[1];
    const float* b_in  = (const float*)d_in[2];
    const float* ln_g  = (const float*)d_in[3];
    const float* ln_b  = (const float*)d_in[4];
    const float* w_out = (const float*)d_in[5];
    const float* b_out = (const float*)d_in[6];
    float* out = (float*)d_out;

    kFused<<<128, NT>>>(inp, w_in, b_in, ln_g, ln_b, w_out, b_out, out);
}

// round 14
// speedup vs baseline: 1.1052x; 1.1052x over previous
#include <cuda_runtime.h>
#include <math.h>

#define S    128
#define Dm   256
#define H    8
#define HD   32
#define KF   40          // feature order (5 chunks of 8, 10 float4 groups)
#define KP2  44          // smem leading dim for psi in phase 2 (f4 stride 11, odd -> conflict-free)
#define BT   8           // tokens per CTA
#define NT   512         // threads per CTA (16 warps)

// 1/sqrt((8m)!)
#define RSF8  4.980119e-3f
#define RSF16 2.186202e-7f
#define RSF24 1.269544e-12f
#define RSF32 1.949459e-18f
// 1/sqrt(32) folded into psi: scores need no 1/32 scale
#define PSISCL 0.17677670f

// Device scratch
__device__ float g_xln[H][S][HD];
__device__ float g_psi[H][S][KF];

// Fence-free global ticket barrier (128 CTAs, all co-resident wave-1).
__device__ unsigned g_bar;

__device__ __forceinline__ void grid_barrier() {
    __syncthreads();
    if (threadIdx.x == 0) {
        unsigned t;
        asm volatile("atom.add.release.gpu.u32 %0, [%1], 1;"
                     : "=r"(t) : "l"(&g_bar) : "memory");
        const unsigned target = (t & ~127u) + 128u;
        unsigned cur;
        do {
            asm volatile("ld.acquire.gpu.u32 %0, [%1];"
                         : "=r"(cur) : "l"(&g_bar) : "memory");
        } while ((int)(cur - target) < 0);
    }
    __syncthreads();
}

__device__ __forceinline__ float warpsum(float v) {
    #pragma unroll
    for (int o = 16; o > 0; o >>= 1) v += __shfl_xor_sync(0xffffffffu, v, o);
    return v;
}

// 1/sqrt(k), k = 0..39
__device__ __constant__ float c_rsq[KF] = {
    1.0f,          1.0f,          0.70710678f,   0.57735027f,
    0.5f,          0.44721360f,   0.40824829f,   0.37796447f,
    0.35355339f,   0.33333333f,   0.31622777f,   0.30151134f,
    0.28867513f,   0.27735010f,   0.26726124f,   0.25819889f,
    0.25f,         0.24253563f,   0.23570226f,   0.22941573f,
    0.22360680f,   0.21821789f,   0.21320072f,   0.20851441f,
    0.20412415f,   0.2f,          0.19611614f,   0.19245009f,
    0.18898224f,   0.18569534f,   0.18257419f,   0.17960530f,
    0.17677670f,   0.17407766f,   0.17149859f,   0.16903085f,
    0.16666667f,   0.16439899f,   0.16222142f,   0.16012815f
};

__device__ __forceinline__ void feat8_vals(float start, float y, int kbase, float* v) {
    v[0] = start;
    #pragma unroll
    for (int j = 1; j < 8; ++j) v[j] = v[j - 1] * y * c_rsq[kbase + j];
}

// Tree-merge 8 values across 32 lanes (7 shuffles), scatter-store by lane groups.
__device__ __forceinline__ void feat8_reduce_store(const float* v, float* dst,
                                                   int kbase, int lane) {
    const bool p16 = (lane & 16) == 0;
    float a0 = p16 ? v[0] : v[1], b0 = p16 ? v[1] : v[0]; a0 += __shfl_xor_sync(0xffffffffu, b0, 16);
    float a1 = p16 ? v[2] : v[3], b1 = p16 ? v[3] : v[2]; a1 += __shfl_xor_sync(0xffffffffu, b1, 16);
    float a2 = p16 ? v[4] : v[5], b2 = p16 ? v[5] : v[4]; a2 += __shfl_xor_sync(0xffffffffu, b2, 16);
    float a3 = p16 ? v[6] : v[7], b3 = p16 ? v[7] : v[6]; a3 += __shfl_xor_sync(0xffffffffu, b3, 16);
    const bool p8 = (lane & 8) == 0;
    float c0 = p8 ? a0 : a1, d0 = p8 ? a1 : a0; c0 += __shfl_xor_sync(0xffffffffu, d0, 8);
    float c1 = p8 ? a2 : a3, d1 = p8 ? a3 : a2; c1 += __shfl_xor_sync(0xffffffffu, d1, 8);
    const bool p4 = (lane & 4) == 0;
    float e0 = p4 ? c0 : c1, f0 = p4 ? c1 : c0; e0 += __shfl_xor_sync(0xffffffffu, f0, 4);
    e0 += __shfl_xor_sync(0xffffffffu, e0, 2);
    e0 += __shfl_xor_sync(0xffffffffu, e0, 1);
    if ((lane & 3) == 0) {
        int g = lane >> 2;
        int j = ((g & 1) << 2) | (g & 2) | (g >> 2);   // bitrev3
        dst[kbase + j] = e0;
    }
}

// ---- shared memory union ----
// Phase 2: Ps is dead after the score GEMM; cat_s (256 f) aliases its storage.
struct SmA { float As[BT][260]; float Bs[HD][260]; float Pp[4][BT][HD]; };     // 45,696 B
struct SmB { float Ps[S][KP2]; float Xs[S][HD]; float Sc[BT][S]; float Ssum[BT][2]; }; // 43,072 B
#define SMEM_BYTES (sizeof(SmB) > sizeof(SmA) ? sizeof(SmB) : sizeof(SmA))

// ---------------------------------------------------------------------------
// Fused kernel, 2 phases. grid 128 x 512. CTA b: grp = b&15, h = b>>4.
// ---------------------------------------------------------------------------
__global__ void __launch_bounds__(NT, 1) kFused(const float* __restrict__ inp,
                                                const float* __restrict__ w_in,
                                                const float* __restrict__ b_in,
                                                const float* __restrict__ ln_g,
                                                const float* __restrict__ ln_b,
                                                const float* __restrict__ w_out,
                                                const float* __restrict__ b_out,
                                                float* __restrict__ out) {
    __shared__ __align__(16) char smraw[SMEM_BYTES];
    SmA& A  = *reinterpret_cast<SmA*>(smraw);
    SmB& Bm = *reinterpret_cast<SmB*>(smraw);

    const int b    = blockIdx.x;
    const int tid  = threadIdx.x;
    const int lane = tid & 31, wid = tid >> 5;    // 16 warps
    const int grp  = b & 15;                       // token group (8 tokens)
    const int h    = b >> 4;                       // head
    const int t0   = grp * BT;

    // ===================== Phase 1: seed-out + proj + LN + features ==========
    {
        // Seed this CTA's out slice [t0..t0+7, h*32..h*32+32) with bias.
        if (tid < 64) {
            const int r = tid >> 3, c4 = tid & 7;
            float4 bv = *(const float4*)&b_out[h * HD + c4 * 4];
            *(float4*)&out[(t0 + r) * Dm + h * HD + c4 * 4] = bv;
        }

        for (int i = tid; i < BT * 64; i += NT) {
            int r = i >> 6, c4 = i & 63;
            *(float4*)&A.As[r][c4 * 4] = *(const float4*)&inp[(t0 + r) * Dm + c4 * 4];
        }
        for (int i = tid; i < HD * 64; i += NT) {
            int r = i >> 6, c4 = i & 63;
            *(float4*)&A.Bs[r][c4 * 4] = *(const float4*)&w_in[(h * HD + r) * Dm + c4 * 4];
        }
        // L2-prefetch this CTA's w_out column-slice lines
        if (tid < 256) {
            const float* p = w_out + tid * Dm + h * HD;
            asm volatile("prefetch.global.L2 [%0];" :: "l"(p));
        }
        __syncthreads();

        {   // GEMM: kq = wid>>2, tp = wid&3 (2 tokens per warp)
            const int kq = wid >> 2, tp = wid & 3;
            float a0 = 0.f, a1 = 0.f;
            #pragma unroll
            for (int k4 = kq * 16; k4 < kq * 16 + 16; ++k4) {
                float4 bv = *(float4*)&A.Bs[lane][k4 * 4];
                float4 x0 = *(float4*)&A.As[tp * 2 + 0][k4 * 4];
                float4 x1 = *(float4*)&A.As[tp * 2 + 1][k4 * 4];
                a0 = fmaf(x0.x, bv.x, a0); a0 = fmaf(x0.y, bv.y, a0);
                a0 = fmaf(x0.z, bv.z, a0); a0 = fmaf(x0.w, bv.w, a0);
                a1 = fmaf(x1.x, bv.x, a1); a1 = fmaf(x1.y, bv.y, a1);
                a1 = fmaf(x1.z, bv.z, a1); a1 = fmaf(x1.w, bv.w, a1);
            }
            A.Pp[kq][tp * 2 + 0][lane] = a0;
            A.Pp[kq][tp * 2 + 1][lane] = a1;
        }
        __syncthreads();

        // LN (2 warps per token, redundant) + features (3+2 chunks per warp pair)
        const int tok = wid & 7;
        float acc = A.Pp[0][tok][lane] + A.Pp[1][tok][lane]
                  + A.Pp[2][tok][lane] + A.Pp[3][tok][lane]
                  + b_in[h * HD + lane];

        float s1 = acc, s2 = acc * acc;
        #pragma unroll
        for (int o = 16; o > 0; o >>= 1) {
            s1 += __shfl_xor_sync(0xffffffffu, s1, o);
            s2 += __shfl_xor_sync(0xffffffffu, s2, o);
        }
        const float mu  = s1 * (1.0f / 32.0f);
        const float var = fmaf(-mu, mu, s2 * (1.0f / 32.0f));
        const float y   = (acc - mu) * rsqrtf(var + 1e-5f) * ln_g[lane] + ln_b[lane];
        const int   tg  = t0 + tok;
        if (wid < 8) g_xln[h][tg][lane] = y;

        float* dst = &g_psi[h][tg][0];
        const float t0e = __expf(-0.5f * y * y) * PSISCL;   // 1/sqrt(32) folded in
        const float y2 = y * y, y4 = y2 * y2, y8 = y4 * y4, y16 = y8 * y8;
        float va[8], vb[8];
        if (wid < 8) {                          // chunks 0,1,2 (k in [0,24))
            float vc[8];
            feat8_vals(t0e,               y, 0,  va);
            feat8_vals(t0e * y8  * RSF8,  y, 8,  vb);
            feat8_vals(t0e * y16 * RSF16, y, 16, vc);
            feat8_reduce_store(va, dst, 0,  lane);
            feat8_reduce_store(vb, dst, 8,  lane);
            feat8_reduce_store(vc, dst, 16, lane);
        } else {                                // chunks 3,4 (k in [24,40))
            const float y24 = y16 * y8, y32 = y16 * y16;
            feat8_vals(t0e * y24 * RSF24, y, 24, va);
            feat8_vals(t0e * y32 * RSF32, y, 32, vb);
            feat8_reduce_store(va, dst, 24, lane);
            feat8_reduce_store(vb, dst, 32, lane);
        }
    }

    grid_barrier();

    // ========== Phase 2: scores(+exp) + fused AV/normalize + out-proj ==========
    {
        // w_out column slice into registers (L2-hit; overlaps psi load).
        const int dblk = wid & 7, half = wid >> 3;
        const int d = dblk * 32 + lane;
        float4 wreg[8];
        {
            const float* wp = w_out + d * Dm + h * HD;
            #pragma unroll
            for (int j = 0; j < 8; ++j) wreg[j] = *(const float4*)&wp[j * 4];
        }

        const float* psi = &g_psi[h][0][0];
        for (int i = tid; i < S * (KF / 4); i += NT) {
            int r = i / (KF / 4), c4 = i - r * (KF / 4);
            *(float4*)&Bm.Ps[r][c4 * 4] = *(const float4*)&psi[r * KF + c4 * 4];
        }
        const float* xl = &g_xln[h][0][0];
        for (int i = tid; i < S * (HD / 4); i += NT) {
            int r = i >> 3, c4 = i & 7;
            *(float4*)&Bm.Xs[r][c4 * 4] = *(const float4*)&xl[r * HD + c4 * 4];
        }
        __syncthreads();

        // Score GEMM + exp + partial row sums. warp = (row = wid&7, half).
        // lane covers t1 = half*64+lane, t2 = t1+32. Scores in (0,32] -> raw exp safe.
        {
            const int row = wid & 7;
            const int t1 = half * 64 + lane, t2 = t1 + 32;
            float a1a = 0.f, a1b = 0.f, a2a = 0.f, a2b = 0.f;
            #pragma unroll
            for (int kg = 0; kg < KF / 4; kg += 2) {
                float4 rs0 = *(float4*)&Bm.Ps[t0 + row][(kg + 0) * 4];  // broadcast
                float4 rs1 = *(float4*)&Bm.Ps[t0 + row][(kg + 1) * 4];
                float4 u0  = *(float4*)&Bm.Ps[t1][(kg + 0) * 4];
                float4 u1  = *(float4*)&Bm.Ps[t1][(kg + 1) * 4];
                float4 v0  = *(float4*)&Bm.Ps[t2][(kg + 0) * 4];
                float4 v1  = *(float4*)&Bm.Ps[t2][(kg + 1) * 4];
                a1a = fmaf(rs0.x, u0.x, a1a); a1a = fmaf(rs0.y, u0.y, a1a);
                a1a = fmaf(rs0.z, u0.z, a1a); a1a = fmaf(rs0.w, u0.w, a1a);
                a1b = fmaf(rs1.x, u1.x, a1b); a1b = fmaf(rs1.y, u1.y, a1b);
                a1b = fmaf(rs1.z, u1.z, a1b); a1b = fmaf(rs1.w, u1.w, a1b);
                a2a = fmaf(rs0.x, v0.x, a2a); a2a = fmaf(rs0.y, v0.y, a2a);
                a2a = fmaf(rs0.z, v0.z, a2a); a2a = fmaf(rs0.w, v0.w, a2a);
                a2b = fmaf(rs1.x, v1.x, a2b); a2b = fmaf(rs1.y, v1.y, a2b);
                a2b = fmaf(rs1.z, v1.z, a2b); a2b = fmaf(rs1.w, v1.w, a2b);
            }
            const float e1 = __expf(a1a + a1b);
            const float e2 = __expf(a2a + a2b);
            const float psum = warpsum(e1 + e2);
            Bm.Sc[row][t1] = e1;
            Bm.Sc[row][t2] = e2;
            if (lane == 0) Bm.Ssum[row][half] = psum;
        }
        __syncthreads();

        // Fused AV + normalize: warp r (wid<8) does the FULL row, writes cat_s.
        // cat_s aliases the dead Ps storage.
        float* cat_s = &Bm.Ps[0][0];          // [8][32] = 256 floats
        if (wid < 8) {
            const int r = wid;
            float o0 = 0.f, o1 = 0.f;
            #pragma unroll
            for (int t4 = 0; t4 < 32; t4 += 2) {
                float4 p0 = *(float4*)&Bm.Sc[r][(t4 + 0) * 4];     // broadcast
                float4 p1 = *(float4*)&Bm.Sc[r][(t4 + 1) * 4];
                o0 = fmaf(p0.x, Bm.Xs[t4 * 4 + 0][lane], o0);
                o0 = fmaf(p0.y, Bm.Xs[t4 * 4 + 1][lane], o0);
                o0 = fmaf(p0.z, Bm.Xs[t4 * 4 + 2][lane], o0);
                o0 = fmaf(p0.w, Bm.Xs[t4 * 4 + 3][lane], o0);
                o1 = fmaf(p1.x, Bm.Xs[t4 * 4 + 4][lane], o1);
                o1 = fmaf(p1.y, Bm.Xs[t4 * 4 + 5][lane], o1);
                o1 = fmaf(p1.z, Bm.Xs[t4 * 4 + 6][lane], o1);
                o1 = fmaf(p1.w, Bm.Xs[t4 * 4 + 7][lane], o1);
            }
            const float inv = 1.0f / (Bm.Ssum[r][0] + Bm.Ssum[r][1]);
            cat_s[r * 32 + lane] = (o0 + o1) * inv;
        }
        __syncthreads();

        // Partial out-projection: thread = (col d, rows half*4..half*4+3), K = 32.
        {
            const int r0 = half * 4;
            float o0 = 0.f, o1 = 0.f, o2 = 0.f, o3 = 0.f;
            #pragma unroll
            for (int j4 = 0; j4 < 8; ++j4) {
                float4 w = wreg[j4];
                float4 c0 = *(float4*)&cat_s[(r0 + 0) * 32 + j4 * 4];  // broadcast
                float4 c1 = *(float4*)&cat_s[(r0 + 1) * 32 + j4 * 4];
                float4 c2 = *(float4*)&cat_s[(r0 + 2) * 32 + j4 * 4];
                float4 c3 = *(float4*)&cat_s[(r0 + 3) * 32 + j4 * 4];
                o0 = fmaf(c0.x, w.x, o0); o0 = fmaf(c0.y, w.y, o0);
                o0 = fmaf(c0.z, w.z, o0); o0 = fmaf(c0.w, w.w, o0);
                o1 = fmaf(c1.x, w.x, o1); o1 = fmaf(c1.y, w.y, o1);
                o1 = fmaf(c1.z, w.z, o1); o1 = fmaf(c1.w, w.w, o1);
                o2 = fmaf(c2.x, w.x, o2); o2 = fmaf(c2.y, w.y, o2);
                o2 = fmaf(c2.z, w.z, o2); o2 = fmaf(c2.w, w.w, o2);
                o3 = fmaf(c3.x, w.x, o3); o3 = fmaf(c3.y, w.y, o3);
                o3 = fmaf(c3.z, w.z, o3); o3 = fmaf(c3.w, w.w, o3);
            }
            float* op = out + (t0 + r0) * Dm + d;
            asm volatile("red.global.add.f32 [%0], %1;" :: "l"(op + 0 * Dm), "f"(o0) : "memory");
            asm volatile("red.global.add.f32 [%0], %1;" :: "l"(op + 1 * Dm), "f"(o1) : "memory");
            asm volatile("red.global.add.f32 [%0], %1;" :: "l"(op + 2 * Dm), "f"(o2) : "memory");
            asm volatile("red.global.add.f32 [%0], %1;" :: "l"(op + 3 * Dm), "f"(o3) : "memory");
        }
    }
}

// ---------------------------------------------------------------------------
extern "C" void kernel_launch(void* const* d_in, const int* in_sizes, int n_in,
                              void* d_out, int out_size) {
    const float* inp   = (const float*)d_in[0];
    const float* w_in  = (const float*)d_in[1];
    const float* b_in  = (const float*)d_in[2];
    const float* ln_g  = (const float*)d_in[3];
    const float* ln_b  = (const float*)d_in[4];
    const float* w_out = (const float*)d_in[5];
    const float* b_out = (const float*)d_in[6];
    float* out = (float*)d_out;

    kFused<<<128, NT>>>(inp, w_in, b_in, ln_g, ln_b, w_out, b_out, out);
}

// round 15
// speedup vs baseline: 1.1470x; 1.0379x over previous
#include <cuda_runtime.h>
#include <math.h>

#define S    128
#define Dm   256
#define H    8
#define HD   32
#define KF   32          // feature order (4 chunks of 8, 8 float4 groups)
#define KP2  36          // smem leading dim for psi in phase 2 (f4 stride 9, odd -> conflict-free)
#define BT   8           // tokens per CTA
#define NT   512         // threads per CTA (16 warps)

// 1/sqrt((8m)!)
#define RSF8  4.980119e-3f
#define RSF16 2.186202e-7f
#define RSF24 1.269544e-12f
// 1/sqrt(32) folded into psi: scores need no 1/32 scale
#define PSISCL 0.17677670f

// Device scratch
__device__ float g_xln[H][S][HD];
__device__ float g_psi[H][S][KF];

// Fence-free global ticket barrier (128 CTAs, all co-resident wave-1).
__device__ unsigned g_bar;

__device__ __forceinline__ void grid_barrier() {
    __syncthreads();
    if (threadIdx.x == 0) {
        unsigned t;
        asm volatile("atom.add.release.gpu.u32 %0, [%1], 1;"
                     : "=r"(t) : "l"(&g_bar) : "memory");
        const unsigned target = (t & ~127u) + 128u;
        unsigned cur;
        do {
            asm volatile("ld.acquire.gpu.u32 %0, [%1];"
                         : "=r"(cur) : "l"(&g_bar) : "memory");
        } while ((int)(cur - target) < 0);
    }
    __syncthreads();
}

__device__ __forceinline__ float warpsum(float v) {
    #pragma unroll
    for (int o = 16; o > 0; o >>= 1) v += __shfl_xor_sync(0xffffffffu, v, o);
    return v;
}

// 1/sqrt(k), k = 0..31
__device__ __constant__ float c_rsq[KF] = {
    1.0f,          1.0f,          0.70710678f,   0.57735027f,
    0.5f,          0.44721360f,   0.40824829f,   0.37796447f,
    0.35355339f,   0.33333333f,   0.31622777f,   0.30151134f,
    0.28867513f,   0.27735010f,   0.26726124f,   0.25819889f,
    0.25f,         0.24253563f,   0.23570226f,   0.22941573f,
    0.22360680f,   0.21821789f,   0.21320072f,   0.20851441f,
    0.20412415f,   0.2f,          0.19611614f,   0.19245009f,
    0.18898224f,   0.18569534f,   0.18257419f,   0.17960530f
};

__device__ __forceinline__ void feat8_vals(float start, float y, int kbase, float* v) {
    v[0] = start;
    #pragma unroll
    for (int j = 1; j < 8; ++j) v[j] = v[j - 1] * y * c_rsq[kbase + j];
}

// Tree-merge 8 values across 32 lanes (7 shuffles), scatter-store by lane groups.
__device__ __forceinline__ void feat8_reduce_store(const float* v, float* dst,
                                                   int kbase, int lane) {
    const bool p16 = (lane & 16) == 0;
    float a0 = p16 ? v[0] : v[1], b0 = p16 ? v[1] : v[0]; a0 += __shfl_xor_sync(0xffffffffu, b0, 16);
    float a1 = p16 ? v[2] : v[3], b1 = p16 ? v[3] : v[2]; a1 += __shfl_xor_sync(0xffffffffu, b1, 16);
    float a2 = p16 ? v[4] : v[5], b2 = p16 ? v[5] : v[4]; a2 += __shfl_xor_sync(0xffffffffu, b2, 16);
    float a3 = p16 ? v[6] : v[7], b3 = p16 ? v[7] : v[6]; a3 += __shfl_xor_sync(0xffffffffu, b3, 16);
    const bool p8 = (lane & 8) == 0;
    float c0 = p8 ? a0 : a1, d0 = p8 ? a1 : a0; c0 += __shfl_xor_sync(0xffffffffu, d0, 8);
    float c1 = p8 ? a2 : a3, d1 = p8 ? a3 : a2; c1 += __shfl_xor_sync(0xffffffffu, d1, 8);
    const bool p4 = (lane & 4) == 0;
    float e0 = p4 ? c0 : c1, f0 = p4 ? c1 : c0; e0 += __shfl_xor_sync(0xffffffffu, f0, 4);
    e0 += __shfl_xor_sync(0xffffffffu, e0, 2);
    e0 += __shfl_xor_sync(0xffffffffu, e0, 1);
    if ((lane & 3) == 0) {
        int g = lane >> 2;
        int j = ((g & 1) << 2) | (g & 2) | (g >> 2);   // bitrev3
        dst[kbase + j] = e0;
    }
}

// ---- shared memory union ----
// Phase 2: Ps is dead after the score GEMM; cat_s (256 f) aliases its storage.
struct SmA { float As[BT][260]; float Bs[HD][260]; float Pp[4][BT][HD]; };     // 45,696 B
struct SmB { float Ps[S][KP2]; float Xs[S][HD]; float Sc[BT][S]; float Ssum[BT][2]; }; // 38,976 B
#define SMEM_BYTES (sizeof(SmB) > sizeof(SmA) ? sizeof(SmB) : sizeof(SmA))

// ---------------------------------------------------------------------------
// Fused kernel, 2 phases. grid 128 x 512. CTA b: grp = b&15, h = b>>4.
// ---------------------------------------------------------------------------
__global__ void __launch_bounds__(NT, 1) kFused(const float* __restrict__ inp,
                                                const float* __restrict__ w_in,
                                                const float* __restrict__ b_in,
                                                const float* __restrict__ ln_g,
                                                const float* __restrict__ ln_b,
                                                const float* __restrict__ w_out,
                                                const float* __restrict__ b_out,
                                                float* __restrict__ out) {
    __shared__ __align__(16) char smraw[SMEM_BYTES];
    SmA& A  = *reinterpret_cast<SmA*>(smraw);
    SmB& Bm = *reinterpret_cast<SmB*>(smraw);

    const int b    = blockIdx.x;
    const int tid  = threadIdx.x;
    const int lane = tid & 31, wid = tid >> 5;    // 16 warps
    const int grp  = b & 15;                       // token group (8 tokens)
    const int h    = b >> 4;                       // head
    const int t0   = grp * BT;

    // ===================== Phase 1: seed-out + proj + LN + features ==========
    {
        // Seed this CTA's out slice [t0..t0+7, h*32..h*32+32) with bias.
        if (tid < 64) {
            const int r = tid >> 3, c4 = tid & 7;
            float4 bv = *(const float4*)&b_out[h * HD + c4 * 4];
            *(float4*)&out[(t0 + r) * Dm + h * HD + c4 * 4] = bv;
        }

        for (int i = tid; i < BT * 64; i += NT) {
            int r = i >> 6, c4 = i & 63;
            *(float4*)&A.As[r][c4 * 4] = *(const float4*)&inp[(t0 + r) * Dm + c4 * 4];
        }
        for (int i = tid; i < HD * 64; i += NT) {
            int r = i >> 6, c4 = i & 63;
            *(float4*)&A.Bs[r][c4 * 4] = *(const float4*)&w_in[(h * HD + r) * Dm + c4 * 4];
        }
        // L2-prefetch this CTA's w_out column-slice lines
        if (tid < 256) {
            const float* p = w_out + tid * Dm + h * HD;
            asm volatile("prefetch.global.L2 [%0];" :: "l"(p));
        }
        __syncthreads();

        {   // GEMM: kq = wid>>2, tp = wid&3 (2 tokens per warp)
            const int kq = wid >> 2, tp = wid & 3;
            float a0 = 0.f, a1 = 0.f;
            #pragma unroll
            for (int k4 = kq * 16; k4 < kq * 16 + 16; ++k4) {
                float4 bv = *(float4*)&A.Bs[lane][k4 * 4];
                float4 x0 = *(float4*)&A.As[tp * 2 + 0][k4 * 4];
                float4 x1 = *(float4*)&A.As[tp * 2 + 1][k4 * 4];
                a0 = fmaf(x0.x, bv.x, a0); a0 = fmaf(x0.y, bv.y, a0);
                a0 = fmaf(x0.z, bv.z, a0); a0 = fmaf(x0.w, bv.w, a0);
                a1 = fmaf(x1.x, bv.x, a1); a1 = fmaf(x1.y, bv.y, a1);
                a1 = fmaf(x1.z, bv.z, a1); a1 = fmaf(x1.w, bv.w, a1);
            }
            A.Pp[kq][tp * 2 + 0][lane] = a0;
            A.Pp[kq][tp * 2 + 1][lane] = a1;
        }
        __syncthreads();

        // LN (2 warps per token, redundant) + features (2 chunks per warp, balanced)
        const int tok = wid & 7;
        float acc = A.Pp[0][tok][lane] + A.Pp[1][tok][lane]
                  + A.Pp[2][tok][lane] + A.Pp[3][tok][lane]
                  + b_in[h * HD + lane];

        float s1 = acc, s2 = acc * acc;
        #pragma unroll
        for (int o = 16; o > 0; o >>= 1) {
            s1 += __shfl_xor_sync(0xffffffffu, s1, o);
            s2 += __shfl_xor_sync(0xffffffffu, s2, o);
        }
        const float mu  = s1 * (1.0f / 32.0f);
        const float var = fmaf(-mu, mu, s2 * (1.0f / 32.0f));
        const float y   = (acc - mu) * rsqrtf(var + 1e-5f) * ln_g[lane] + ln_b[lane];
        const int   tg  = t0 + tok;
        if (wid < 8) g_xln[h][tg][lane] = y;

        float* dst = &g_psi[h][tg][0];
        const float t0e = __expf(-0.5f * y * y) * PSISCL;   // 1/sqrt(32) folded in
        const float y2 = y * y, y4 = y2 * y2, y8 = y4 * y4;
        float va[8], vb[8];
        if (wid < 8) {                          // chunks 0,1 (k in [0,16))
            feat8_vals(t0e,              y, 0, va);
            feat8_vals(t0e * y8 * RSF8,  y, 8, vb);
            feat8_reduce_store(va, dst, 0, lane);
            feat8_reduce_store(vb, dst, 8, lane);
        } else {                                // chunks 2,3 (k in [16,32))
            const float y16 = y8 * y8, y24 = y16 * y8;
            feat8_vals(t0e * y16 * RSF16, y, 16, va);
            feat8_vals(t0e * y24 * RSF24, y, 24, vb);
            feat8_reduce_store(va, dst, 16, lane);
            feat8_reduce_store(vb, dst, 24, lane);
        }
    }

    grid_barrier();

    // ========== Phase 2: scores(+exp) + fused AV/normalize + out-proj ==========
    {
        // w_out column slice into registers (L2-hit; overlaps psi load).
        const int dblk = wid & 7, half = wid >> 3;
        const int d = dblk * 32 + lane;
        float4 wreg[8];
        {
            const float* wp = w_out + d * Dm + h * HD;
            #pragma unroll
            for (int j = 0; j < 8; ++j) wreg[j] = *(const float4*)&wp[j * 4];
        }

        const float* psi = &g_psi[h][0][0];
        #pragma unroll
        for (int i = tid; i < S * (KF / 4); i += NT) {      // 1024 f4: 2/thread
            int r = i >> 3, c4 = i & 7;
            *(float4*)&Bm.Ps[r][c4 * 4] = *(const float4*)&psi[r * KF + c4 * 4];
        }
        const float* xl = &g_xln[h][0][0];
        #pragma unroll
        for (int i = tid; i < S * (HD / 4); i += NT) {      // 1024 f4: 2/thread
            int r = i >> 3, c4 = i & 7;
            *(float4*)&Bm.Xs[r][c4 * 4] = *(const float4*)&xl[r * HD + c4 * 4];
        }
        __syncthreads();

        // Score GEMM + exp + partial row sums. warp = (row = wid&7, half).
        // lane covers t1 = half*64+lane, t2 = t1+32. Scores in (0,32] -> raw exp safe.
        {
            const int row = wid & 7;
            const int t1 = half * 64 + lane, t2 = t1 + 32;
            float a1a = 0.f, a1b = 0.f, a2a = 0.f, a2b = 0.f;
            #pragma unroll
            for (int kg = 0; kg < KF / 4; kg += 2) {
                float4 rs0 = *(float4*)&Bm.Ps[t0 + row][(kg + 0) * 4];  // broadcast
                float4 rs1 = *(float4*)&Bm.Ps[t0 + row][(kg + 1) * 4];
                float4 u0  = *(float4*)&Bm.Ps[t1][(kg + 0) * 4];
                float4 u1  = *(float4*)&Bm.Ps[t1][(kg + 1) * 4];
                float4 v0  = *(float4*)&Bm.Ps[t2][(kg + 0) * 4];
                float4 v1  = *(float4*)&Bm.Ps[t2][(kg + 1) * 4];
                a1a = fmaf(rs0.x, u0.x, a1a); a1a = fmaf(rs0.y, u0.y, a1a);
                a1a = fmaf(rs0.z, u0.z, a1a); a1a = fmaf(rs0.w, u0.w, a1a);
                a1b = fmaf(rs1.x, u1.x, a1b); a1b = fmaf(rs1.y, u1.y, a1b);
                a1b = fmaf(rs1.z, u1.z, a1b); a1b = fmaf(rs1.w, u1.w, a1b);
                a2a = fmaf(rs0.x, v0.x, a2a); a2a = fmaf(rs0.y, v0.y, a2a);
                a2a = fmaf(rs0.z, v0.z, a2a); a2a = fmaf(rs0.w, v0.w, a2a);
                a2b = fmaf(rs1.x, v1.x, a2b); a2b = fmaf(rs1.y, v1.y, a2b);
                a2b = fmaf(rs1.z, v1.z, a2b); a2b = fmaf(rs1.w, v1.w, a2b);
            }
            const float e1 = __expf(a1a + a1b);
            const float e2 = __expf(a2a + a2b);
            const float psum = warpsum(e1 + e2);
            Bm.Sc[row][t1] = e1;
            Bm.Sc[row][t2] = e2;
            if (lane == 0) Bm.Ssum[row][half] = psum;
        }
        __syncthreads();

        // Fused AV + normalize: warp r (wid<8) does the FULL row, writes cat_s.
        // cat_s aliases the dead Ps storage.
        float* cat_s = &Bm.Ps[0][0];          // [8][32] = 256 floats
        if (wid < 8) {
            const int r = wid;
            float o0 = 0.f, o1 = 0.f;
            #pragma unroll
            for (int t4 = 0; t4 < 32; t4 += 2) {
                float4 p0 = *(float4*)&Bm.Sc[r][(t4 + 0) * 4];     // broadcast
                float4 p1 = *(float4*)&Bm.Sc[r][(t4 + 1) * 4];
                o0 = fmaf(p0.x, Bm.Xs[t4 * 4 + 0][lane], o0);
                o0 = fmaf(p0.y, Bm.Xs[t4 * 4 + 1][lane], o0);
                o0 = fmaf(p0.z, Bm.Xs[t4 * 4 + 2][lane], o0);
                o0 = fmaf(p0.w, Bm.Xs[t4 * 4 + 3][lane], o0);
                o1 = fmaf(p1.x, Bm.Xs[t4 * 4 + 4][lane], o1);
                o1 = fmaf(p1.y, Bm.Xs[t4 * 4 + 5][lane], o1);
                o1 = fmaf(p1.z, Bm.Xs[t4 * 4 + 6][lane], o1);
                o1 = fmaf(p1.w, Bm.Xs[t4 * 4 + 7][lane], o1);
            }
            const float inv = 1.0f / (Bm.Ssum[r][0] + Bm.Ssum[r][1]);
            cat_s[r * 32 + lane] = (o0 + o1) * inv;
        }
        __syncthreads();

        // Partial out-projection: thread = (col d, rows half*4..half*4+3), K = 32.
        {
            const int r0 = half * 4;
            float o0 = 0.f, o1 = 0.f, o2 = 0.f, o3 = 0.f;
            #pragma unroll
            for (int j4 = 0; j4 < 8; ++j4) {
                float4 w = wreg[j4];
                float4 c0 = *(float4*)&cat_s[(r0 + 0) * 32 + j4 * 4];  // broadcast
                float4 c1 = *(float4*)&cat_s[(r0 + 1) * 32 + j4 * 4];
                float4 c2 = *(float4*)&cat_s[(r0 + 2) * 32 + j4 * 4];
                float4 c3 = *(float4*)&cat_s[(r0 + 3) * 32 + j4 * 4];
                o0 = fmaf(c0.x, w.x, o0); o0 = fmaf(c0.y, w.y, o0);
                o0 = fmaf(c0.z, w.z, o0); o0 = fmaf(c0.w, w.w, o0);
                o1 = fmaf(c1.x, w.x, o1); o1 = fmaf(c1.y, w.y, o1);
                o1 = fmaf(c1.z, w.z, o1); o1 = fmaf(c1.w, w.w, o1);
                o2 = fmaf(c2.x, w.x, o2); o2 = fmaf(c2.y, w.y, o2);
                o2 = fmaf(c2.z, w.z, o2); o2 = fmaf(c2.w, w.w, o2);
                o3 = fmaf(c3.x, w.x, o3); o3 = fmaf(c3.y, w.y, o3);
                o3 = fmaf(c3.z, w.z, o3); o3 = fmaf(c3.w, w.w, o3);
            }
            float* op = out + (t0 + r0) * Dm + d;
            asm volatile("red.global.add.f32 [%0], %1;" :: "l"(op + 0 * Dm), "f"(o0) : "memory");
            asm volatile("red.global.add.f32 [%0], %1;" :: "l"(op + 1 * Dm), "f"(o1) : "memory");
            asm volatile("red.global.add.f32 [%0], %1;" :: "l"(op + 2 * Dm), "f"(o2) : "memory");
            asm volatile("red.global.add.f32 [%0], %1;" :: "l"(op + 3 * Dm), "f"(o3) : "memory");
        }
    }
}

// ---------------------------------------------------------------------------
extern "C" void kernel_launch(void* const* d_in, const int* in_sizes, int n_in,
                              void* d_out, int out_size) {
    const float* inp   = (const float*)d_in[0];
    const float* w_in  = (const float*)d_in[1];
    const float* b_in  = (const float*)d_in[2];
    const float* ln_g  = (const float*)d_in[3];
    const float* ln_b  = (const float*)d_in[4];
    const float* w_out = (const float*)d_in[5];
    const float* b_out = (const float*)d_in[6];
    float* out = (float*)d_out;

    kFused<<<128, NT>>>(inp, w_in, b_in, ln_g, ln_b, w_out, b_out, out);
}